// round 15
// baseline (speedup 1.0000x reference)
#include <cuda_runtime.h>
#include <cuda_bf16.h>
#include <cstdint>

// ---------------------------------------------------------------------------
// Problem constants
// ---------------------------------------------------------------------------
#define BATCH   8192
#define SEQ     8
#define HID     2048
#define NEXP    64
#define TOPK    8
#define ROWSTR  (SEQ * HID)

// GEMM config (core byte-identical to the R11/R14 passing kernels): BM=64,
// split-K=2, warps 0-3 consumers (m32n32, LDSM A + direct-LDG B frags + MMA),
// warps 4-7 producers (LDG A f32 -> split3 -> STS), 2-stage A pipeline.
// NEW: B-split runs as an inline prologue (grid is one co-resident wave:
// 256 CTAs <= 148 SMs x 2 CTAs/SM), guarded by a grid-wide ticket spin.
#define BM      64
#define KT      64
#define KSPL    2
#define KHALF   (HID / KSPL)       // 1024
#define NT      (KHALF / KT)       // 16
#define GCTAS   ((BATCH / BM) * KSPL)  // 256 CTAs

#define A_PL    8192               // 64 rows x 128B
#define ABUF    (3 * A_PL)         // 24576
#define STAGE   ABUF
#define SM_ALLOC (2 * STAGE + 1024)   // 50176 -> 2 CTAs/SM

#define NCH     (HID / 16)         // 128 k16 chunks

// Router config: 256 blocks x 512 threads, 16 warps x 2 rows = 32 rows/block
#define RBLK    256
#define RTHR    512
#define RROWS   32

// Scratch (no allocation allowed)
__device__ float    g_partial[KSPL][BATCH * NEXP];  // 4 MB
__device__ uint32_t g_bfrag[3 * 8 * NCH * 64];      // 768 KB, frag-ordered B
__device__ float    g_bimp[RBLK][NEXP];
__device__ int      g_bcnt[RBLK][NEXP];
__device__ unsigned g_ready;    // gemm prologue ticket (reset by router)
__device__ unsigned g_done;     // router ticket (reset by router)

// ---------------------------------------------------------------------------
// helpers
// ---------------------------------------------------------------------------
__device__ __forceinline__ uint32_t smem_to_u32(const void* p) {
    uint32_t a;
    asm("{ .reg .u64 t; cvta.to.shared.u64 t, %1; cvt.u32.u64 %0, t; }"
        : "=r"(a) : "l"(p));
    return a;
}
__device__ __forceinline__ void ldsm4(uint32_t* r, uint32_t addr) {
    asm volatile("ldmatrix.sync.aligned.m8n8.x4.shared.b16 {%0,%1,%2,%3}, [%4];"
                 : "=r"(r[0]), "=r"(r[1]), "=r"(r[2]), "=r"(r[3]) : "r"(addr));
}
__device__ __forceinline__ void mma16816(float* d, const uint32_t* a,
                                         const uint32_t* b) {
    asm volatile(
        "mma.sync.aligned.m16n8k16.row.col.f32.bf16.bf16.f32 "
        "{%0,%1,%2,%3}, {%4,%5,%6,%7}, {%8,%9}, {%0,%1,%2,%3};"
        : "+f"(d[0]), "+f"(d[1]), "+f"(d[2]), "+f"(d[3])
        : "r"(a[0]), "r"(a[1]), "r"(a[2]), "r"(a[3]), "r"(b[0]), "r"(b[1]));
}
__device__ __forceinline__ uint32_t pack_bf16(float lo, float hi) {
    uint32_t r;
    asm("cvt.rn.bf16x2.f32 %0, %1, %2;" : "=r"(r) : "f"(hi), "f"(lo));
    return r;
}
// fp32 -> 3x bf16 split (byte-identical to the R8/R11/R14-passing kernels)
__device__ __forceinline__ void split3(float x, float y,
                                       uint32_t& h, uint32_t& m, uint32_t& l) {
    h = pack_bf16(x, y);
    float hx = __uint_as_float(h << 16);
    float hy = __uint_as_float(h & 0xffff0000u);
    float rx = x - hx, ry = y - hy;
    m = pack_bf16(rx, ry);
    float mx = __uint_as_float(m << 16);
    float my = __uint_as_float(m & 0xffff0000u);
    l = pack_bf16(rx - mx, ry - my);
}
__device__ __forceinline__ void sts64(uint32_t addr, uint32_t a, uint32_t b) {
    asm volatile("st.shared.v2.b32 [%0], {%1, %2};"
                 :: "r"(addr), "r"(a), "r"(b) : "memory");
}
#define BAR_SYNC(id)   asm volatile("bar.sync %0, 256;"   :: "r"(id) : "memory")
#define BAR_ARRIVE(id) asm volatile("bar.arrive %0, 256;" :: "r"(id) : "memory")

__device__ __forceinline__ int redux_max_s32(int v) {
    int r;
    asm("redux.sync.max.s32 %0, %1, 0xffffffff;" : "=r"(r) : "r"(v));
    return r;
}
__device__ __forceinline__ unsigned redux_max_u32(unsigned v) {
    unsigned r;
    asm("redux.sync.max.u32 %0, %1, 0xffffffff;" : "=r"(r) : "r"(v));
    return r;
}
__device__ __forceinline__ unsigned fenc(float f) {
    int b = __float_as_int(f);
    return (unsigned)(b ^ ((b >> 31) | 0x80000000));
}
__device__ __forceinline__ float fdec(unsigned u) {
    int b = (u & 0x80000000u) ? (int)(u ^ 0x80000000u) : (int)~u;
    return __int_as_float(b);
}

// ---------------------------------------------------------------------------
// Kernel 1: HMMA logits GEMM (R11/R14 core) with inline B-split prologue.
// ---------------------------------------------------------------------------
__global__ void __launch_bounds__(256, 2)
gemm_tc(const float* __restrict__ hs, const float* __restrict__ gw) {
    extern __shared__ char smem_raw[];
    const uint32_t sb = (smem_to_u32(smem_raw) + 1023u) & ~1023u;

    const int tid  = threadIdx.x;
    const int wid  = tid >> 5;
    const int lane = tid & 31;
    const int m0   = blockIdx.x * BM;
    const int sp   = blockIdx.y;
    const int k0   = sp * KHALF;

    // ---- inline B-split prologue: 1 float2 per thread, grid covers all ----
    // (byte layout identical to the standalone bsplit kernel)
    {
        const int cta = blockIdx.y * (BATCH / BM) + blockIdx.x;  // 0..255
        const int id  = cta * 256 + tid;                         // 0..65535
        int half = id & 1;
        int t    = (id >> 1) & 31;
        int c    = (id >> 6) & 127;
        int g    = id >> 13;
        int n   = g * 8 + (t >> 2);
        int k0p = c * 16 + (t & 3) * 2 + half * 8;
        float2 v = *(const float2*)(gw + (size_t)n * HID + k0p);
        uint32_t h, m, l;
        split3(v.x, v.y, h, m, l);
        int fi = (g * NCH + c) * 64 + t * 2 + half;
        const int PL = 8 * NCH * 64;
        g_bfrag[fi]          = h;
        g_bfrag[PL + fi]     = m;
        g_bfrag[2 * PL + fi] = l;
        __threadfence();
        __syncthreads();
        if (tid == 0) atomicAdd(&g_ready, 1u);
    }

    if (wid < 4) {
        // =================== CONSUMER ===================
        // wait until ALL CTAs have published their B-frag slice
        // (grid is one co-resident wave -> no deadlock; producers are
        // meanwhile already streaming A tile 0 from DRAM)
        while (*(volatile unsigned*)&g_ready < (unsigned)GCTAS) { }
        __threadfence();

        const int wm = (wid & 1) * 32;
        const int wn = (wid >> 1) * 32;
        const int gbase = wn >> 3;

        uint32_t abase[2], amask[2];
#pragma unroll
        for (int mt = 0; mt < 2; mt++) {
            int row = wm + mt * 16 + (lane & 15);
            abase[mt] = (uint32_t)(row * 128 + (lane >> 4) * 16);
            amask[mt] = (uint32_t)((row & 7) << 4);
        }

        float acc[2][4][4];
#pragma unroll
        for (int a = 0; a < 2; a++)
#pragma unroll
            for (int b = 0; b < 4; b++)
#pragma unroll
                for (int c = 0; c < 4; c++) acc[a][b][c] = 0.0f;

        const int pa[6] = {0, 0, 1, 0, 2, 1};
        const int pb[6] = {0, 1, 0, 2, 0, 1};

        const int PL = 8 * NCH * 64;
        const int csp = sp * (KHALF / 16);

        uint2 bb0[3][4], bb1[3][4];
#define LOAD_B(dst, cc) do {                                                  \
    _Pragma("unroll")                                                         \
    for (int p = 0; p < 3; p++) {                                             \
        _Pragma("unroll")                                                     \
        for (int j = 0; j < 4; j++)                                           \
            (dst)[p][j] = __ldg((const uint2*)&g_bfrag[                       \
                p * PL + ((gbase + j) * NCH + (csp + (cc))) * 64] + lane);    \
    } } while (0)

        LOAD_B(bb0, 0);

        for (int t = 0; t < NT; t++) {
            const int buf = t & 1;
            const uint32_t aBase = sb + (uint32_t)buf * STAGE;

            BAR_SYNC(1 + buf);

#pragma unroll
            for (int kc = 0; kc < 4; kc++) {
                uint32_t af[3][2][4];
#pragma unroll
                for (int p = 0; p < 3; p++)
#pragma unroll
                    for (int mt = 0; mt < 2; mt++)
                        ldsm4(af[p][mt],
                              aBase + p * A_PL + ((abase[mt] + kc * 32) ^ amask[mt]));

                if (kc < 3) {
                    if (kc & 1) { LOAD_B(bb0, t * 4 + kc + 1); }
                    else        { LOAD_B(bb1, t * 4 + kc + 1); }
                } else if (t + 1 < NT) {
                    LOAD_B(bb0, t * 4 + 4);
                }

#pragma unroll
                for (int pr = 0; pr < 6; pr++) {
#pragma unroll
                    for (int mt = 0; mt < 2; mt++) {
#pragma unroll
                        for (int j = 0; j < 4; j++) {
                            const uint2* bf = (kc & 1) ? &bb1[pb[pr]][j]
                                                       : &bb0[pb[pr]][j];
                            mma16816(acc[mt][j], af[pa[pr]][mt],
                                     (const uint32_t*)bf);
                        }
                    }
                }
            }
            if (t + 2 < NT) BAR_ARRIVE(3 + buf);
        }
#undef LOAD_B

        const int gr = m0 + wm + (lane >> 2);
        const int gc = wn + (lane & 3) * 2;
#pragma unroll
        for (int mt = 0; mt < 2; mt++) {
#pragma unroll
            for (int j = 0; j < 4; j++) {
                int row = gr + mt * 16;
                int col = gc + j * 8;
                *(float2*)&g_partial[sp][(size_t)row * NEXP + col] =
                    make_float2(acc[mt][j][0], acc[mt][j][1]);
                *(float2*)&g_partial[sp][(size_t)(row + 8) * NEXP + col] =
                    make_float2(acc[mt][j][2], acc[mt][j][3]);
            }
        }
    } else {
        // =================== PRODUCER (A only) ===================
        const int wt = tid & 127;

        float4 ar[8], arn[8];
#define LOAD_A(t, dst) do {                                                   \
    int kk = k0 + (t) * KT;                                                   \
    _Pragma("unroll")                                                         \
    for (int i = 0; i < 8; i++) {                                             \
        int lin = wt + i * 128; int row = lin >> 4; int c4 = lin & 15;        \
        (dst)[i] = *(const float4*)(hs + (size_t)(m0 + row) * ROWSTR + kk + c4 * 4); \
    } } while (0)

        LOAD_A(0, ar);

        for (int t = 0; t < NT; t++) {
            const int buf = t & 1;
            const uint32_t aBase = sb + (uint32_t)buf * STAGE;

            if (t + 1 < NT) LOAD_A(t + 1, arn);
            if (t >= 2) BAR_SYNC(3 + buf);

#pragma unroll
            for (int i = 0; i < 8; i++) {
                int lin = wt + i * 128; int row = lin >> 4; int c4 = lin & 15;
                uint32_t off = (uint32_t)(row * 128 + c4 * 8);
                uint32_t sw  = off ^ ((off >> 3) & 0x70u);
                uint32_t h0, mm0, l0, h1, mm1, l1;
                split3(ar[i].x, ar[i].y, h0, mm0, l0);
                split3(ar[i].z, ar[i].w, h1, mm1, l1);
                sts64(aBase + sw,            h0,  h1);
                sts64(aBase + A_PL + sw,     mm0, mm1);
                sts64(aBase + 2 * A_PL + sw, l0,  l1);
            }
            BAR_ARRIVE(1 + buf);

#pragma unroll
            for (int i = 0; i < 8; i++) ar[i] = arn[i];
        }
#undef LOAD_A
    }
}

// ---------------------------------------------------------------------------
// Kernel 2: router, 2 rows per warp (interleaved redux chains for ILP).
// Last block computes aux AND resets the tickets for the next graph replay.
// ---------------------------------------------------------------------------
__global__ void __launch_bounds__(RTHR)
router_kernel(float* __restrict__ out) {
    __shared__ float s_pr[RROWS][NEXP];
    __shared__ int   s_cnt[NEXP];
    __shared__ int   s_last;
    const int tid  = threadIdx.x;
    const int lane = tid & 31;
    const int w    = tid >> 5;                 // 0..15
    if (tid < NEXP) s_cnt[tid] = 0;
    __syncthreads();

    const int row0 = blockIdx.x * RROWS + w * 2;

    float l0[2], l1[2];
#pragma unroll
    for (int rr = 0; rr < 2; rr++) {
        const float* p0p = &g_partial[0][(size_t)(row0 + rr) * NEXP];
        const float* p1p = &g_partial[1][(size_t)(row0 + rr) * NEXP];
        l0[rr] = p0p[lane] + p1p[lane];
        l1[rr] = p0p[lane + 32] + p1p[lane + 32];
    }

    float p0[2], p1[2];
    {
        unsigned ea = redux_max_u32(fenc(fmaxf(l0[0], l1[0])));
        unsigned eb = redux_max_u32(fenc(fmaxf(l0[1], l1[1])));
        float ma = fdec(ea), mb = fdec(eb);
        p0[0] = __expf(l0[0] - ma); p1[0] = __expf(l1[0] - ma);
        p0[1] = __expf(l0[1] - mb); p1[1] = __expf(l1[1] - mb);
        float sa = p0[0] + p1[0], sb2 = p0[1] + p1[1];
#pragma unroll
        for (int off = 16; off; off >>= 1) {
            sa  += __shfl_xor_sync(0xffffffffu, sa, off);
            sb2 += __shfl_xor_sync(0xffffffffu, sb2, off);
        }
        float ia = 1.0f / sa, ib = 1.0f / sb2;
        p0[0] *= ia; p1[0] *= ia;
        p0[1] *= ib; p1[1] *= ib;
    }

    s_pr[w * 2 + 0][lane]      = p0[0];
    s_pr[w * 2 + 0][lane + 32] = p1[0];
    s_pr[w * 2 + 1][lane]      = p0[1];
    s_pr[w * 2 + 1][lane + 32] = p1[1];

    const int NEG1 = 0xBF800000;
    int b0i[2] = { __float_as_int(p0[0]), __float_as_int(p0[1]) };
    int b1i[2] = { __float_as_int(p1[0]), __float_as_int(p1[1]) };
    bool sel0[2] = {false, false}, sel1[2] = {false, false};
    float wsum[2] = {0.0f, 0.0f}, myv[2] = {0.0f, 0.0f};
    int myi[2] = {0, 0};
#pragma unroll
    for (int it = 0; it < TOPK; it++) {
        int ca0 = sel0[0] ? NEG1 : b0i[0];
        int ca1 = sel1[0] ? NEG1 : b1i[0];
        int cb0 = sel0[1] ? NEG1 : b0i[1];
        int cb1 = sel1[1] ? NEG1 : b1i[1];
        int mva = redux_max_s32(ca0 > ca1 ? ca0 : ca1);
        int mvb = redux_max_s32(cb0 > cb1 ? cb0 : cb1);
        unsigned qa0 = __ballot_sync(0xffffffffu, ca0 == mva);
        unsigned qa1 = __ballot_sync(0xffffffffu, ca1 == mva);
        unsigned qb0 = __ballot_sync(0xffffffffu, cb0 == mvb);
        unsigned qb1 = __ballot_sync(0xffffffffu, cb1 == mvb);
        int ida = qa0 ? (__ffs(qa0) - 1) : (__ffs(qa1) + 31);
        int idb = qb0 ? (__ffs(qb0) - 1) : (__ffs(qb1) + 31);
        wsum[0] += __int_as_float(mva);
        wsum[1] += __int_as_float(mvb);
        if (ida == lane)           sel0[0] = true;
        else if (ida == lane + 32) sel1[0] = true;
        if (idb == lane)           sel0[1] = true;
        else if (idb == lane + 32) sel1[1] = true;
        if (lane == it) {
            myv[0] = __int_as_float(mva); myi[0] = ida;
            myv[1] = __int_as_float(mvb); myi[1] = idb;
        }
        if (lane == 0) {
            atomicAdd(&s_cnt[ida], 1);
            atomicAdd(&s_cnt[idb], 1);
        }
    }

#pragma unroll
    for (int rr = 0; rr < 2; rr++) {
        float invw = 1.0f / fmaxf(wsum[rr], 1e-8f);
        if (lane < TOPK) {
            const int grow = row0 + rr;
            out[(size_t)grow * TOPK + lane] = (float)myi[rr];
            out[(size_t)BATCH * TOPK + (size_t)grow * TOPK + lane] =
                myv[rr] * invw;
        }
    }

    __syncthreads();

    if (tid < NEXP) {
        float si = 0.0f;
#pragma unroll
        for (int ww = 0; ww < RROWS; ww++) si += s_pr[ww][tid];
        g_bimp[blockIdx.x][tid] = si;
        g_bcnt[blockIdx.x][tid] = s_cnt[tid];
        __threadfence();
    }
    __syncthreads();
    if (tid == 0) {
        unsigned tk = atomicAdd(&g_done, 1u);
        s_last = (tk == gridDim.x - 1) ? 1 : 0;
    }
    __syncthreads();

    if (s_last) {
        __shared__ float s_ri[8][NEXP];
        __shared__ int   s_rc[8][NEXP];
        const int e  = tid & 63;
        const int ch = tid >> 6;            // 0..7
        float si = 0.0f;
        int   sc = 0;
#pragma unroll 8
        for (int b = ch * (RBLK / 8); b < (ch + 1) * (RBLK / 8); b++) {
            si += *(volatile float*)&g_bimp[b][e];
            sc += *(volatile int*)&g_bcnt[b][e];
        }
        s_ri[ch][e] = si;
        s_rc[ch][e] = sc;
        __syncthreads();
        if (tid < NEXP) {
            float ti = 0.0f;
            int   tc = 0;
#pragma unroll
            for (int c = 0; c < 8; c++) { ti += s_ri[c][tid]; tc += s_rc[c][tid]; }
            s_ri[0][tid] = (float)NEXP * (ti / (float)BATCH) *
                           ((float)tc / (float)(BATCH * TOPK));
        }
        __syncthreads();
        if (tid == 0) {
            float s = 0.0f;
#pragma unroll
            for (int i = 0; i < NEXP; i++) s += s_ri[0][i];
            out[(size_t)2 * BATCH * TOPK] = s;
            // reset tickets for the next graph replay (all blocks already
            // ticked g_done; next gemm launch is stream-ordered after us)
            g_done  = 0u;
            g_ready = 0u;
        }
    }
}

// ---------------------------------------------------------------------------
extern "C" void kernel_launch(void* const* d_in, const int* in_sizes, int n_in,
                              void* d_out, int out_size) {
    const float* hs  = (const float*)d_in[0];
    const float* gw  = (const float*)d_in[1];
    float*       out = (float*)d_out;

    cudaFuncSetAttribute(gemm_tc, cudaFuncAttributeMaxDynamicSharedMemorySize,
                         SM_ALLOC);
    gemm_tc<<<dim3(BATCH / BM, KSPL), 256, SM_ALLOC>>>(hs, gw);
    router_kernel<<<RBLK, RTHR>>>(out);
}